// round 14
// baseline (speedup 1.0000x reference)
#include <cuda_runtime.h>
#include <cuda_bf16.h>
#include <math.h>
#include <stdint.h>

// Problem constants
constexpr int NB  = 4;
constexpr int NC  = 64;
constexpr int NHW = 4096;     // 64*64
constexpr int NKD = 576;      // C*9
constexpr int NBLK = 32;      // 4096 / 128 row-blocks
constexpr int NPAIR = NBLK * (NBLK + 1) / 2;   // 528 upper-tri tiles
constexpr int NTILE = NPAIR * NB;              // 2112 work items

// Split-K bf16 GEMM config
constexpr int KP     = 1152;          // stored K' = [hi(576) | lo(576)]
constexpr int ROWB   = KP * 2;        // 2304 bytes per n-row
constexpr int NCHUNK = 27;            // 27 x 64 = effective K 1728 (hihi+lohi+hilo)

constexpr int STAGE  = 32768;         // A 16KB + B 16KB per stage
constexpr int SMEMB  = 3 * STAGE;     // 96 KB, 3-stage pipeline
constexpr int ESTRIDE = 130;          // epilogue smem row stride (floats)

// Scratch (static __device__: no allocations allowed)
__device__ __nv_bfloat16 g_za[(size_t)NB * NHW * KP];   // [b][n][hi|lo]  ~37.7MB
__device__ float g_norm[NB * NC * 9];                   // per-(b,c,j) L2 norms
__device__ float g_cv[(size_t)NB * NHW * NBLK * 3];     // candidate values 6.3MB
__device__ int   g_ci[(size_t)NB * NHW * NBLK * 3];     // candidate indices 6.3MB

// ---------------------------------------------------------------------------
// PTX helpers (sm_80-era: safe for plain sm_103 ptxas target)
// ---------------------------------------------------------------------------
__device__ __forceinline__ uint32_t s2u(const void* p) {
    uint32_t a;
    asm("{ .reg .u64 t; cvta.to.shared.u64 t, %1; cvt.u32.u64 %0, t; }"
        : "=r"(a) : "l"(p));
    return a;
}
__device__ __forceinline__ void cp16(uint32_t s, const void* g) {
    asm volatile("cp.async.cg.shared.global [%0], [%1], 16;"
                 :: "r"(s), "l"(g) : "memory");
}
#define CP_COMMIT()  asm volatile("cp.async.commit_group;" ::: "memory")
#define CP_WAIT1()   asm volatile("cp.async.wait_group 1;" ::: "memory")

#define LDSM4(r0, r1, r2, r3, a) \
    asm volatile("ldmatrix.sync.aligned.m8n8.x4.shared.b16 {%0,%1,%2,%3}, [%4];" \
                 : "=r"(r0), "=r"(r1), "=r"(r2), "=r"(r3) : "r"(a))

__device__ __forceinline__ void mma16816(float* c, uint32_t a0, uint32_t a1,
                                         uint32_t a2, uint32_t a3,
                                         uint32_t b0, uint32_t b1) {
    asm volatile(
        "mma.sync.aligned.m16n8k16.row.col.f32.bf16.bf16.f32 "
        "{%0,%1,%2,%3}, {%4,%5,%6,%7}, {%8,%9}, {%0,%1,%2,%3};"
        : "+f"(c[0]), "+f"(c[1]), "+f"(c[2]), "+f"(c[3])
        : "r"(a0), "r"(a1), "r"(a2), "r"(a3), "r"(b0), "r"(b1));
}

// ---------------------------------------------------------------------------
// Kernel 1: shifted norms via border decomposition.
// ---------------------------------------------------------------------------
__global__ void norms_kernel(const float* __restrict__ x) {
    const int bc = blockIdx.x;
    const float* xp = x + (size_t)bc * NHW;

    float s = 0.f, r0 = 0.f, r63 = 0.f, cl = 0.f, cr = 0.f;
    for (int idx = threadIdx.x; idx < NHW; idx += blockDim.x) {
        float v = xp[idx]; v *= v;
        const int h = idx >> 6, w = idx & 63;
        s += v;
        if (h == 0)  r0  += v;
        if (h == 63) r63 += v;
        if (w == 0)  cl  += v;
        if (w == 63) cr  += v;
    }
    __shared__ float red[5][256];
    red[0][threadIdx.x] = s;  red[1][threadIdx.x] = r0; red[2][threadIdx.x] = r63;
    red[3][threadIdx.x] = cl; red[4][threadIdx.x] = cr;
    __syncthreads();
    for (int o = 128; o > 0; o >>= 1) {
        if (threadIdx.x < o)
            for (int q = 0; q < 5; ++q) red[q][threadIdx.x] += red[q][threadIdx.x + o];
        __syncthreads();
    }
    if (threadIdx.x == 0) {
        const float S = red[0][0], R0 = red[1][0], R63 = red[2][0];
        const float CL = red[3][0], CR = red[4][0];
        float x00 = xp[0],        x0e = xp[63];
        float xe0 = xp[63 * 64],  xee = xp[63 * 64 + 63];
        x00 *= x00; x0e *= x0e; xe0 *= xe0; xee *= xee;
        #pragma unroll
        for (int kh = 0; kh < 3; ++kh)
            #pragma unroll
            for (int kw = 0; kw < 3; ++kw) {
                float n2 = S;
                if (kh == 0) n2 -= R63;
                if (kh == 2) n2 -= R0;
                if (kw == 0) n2 -= CR;
                if (kw == 2) n2 -= CL;
                if (kh == 0 && kw == 0) n2 += xee;
                if (kh == 0 && kw == 2) n2 += xe0;
                if (kh == 2 && kw == 0) n2 += x0e;
                if (kh == 2 && kw == 2) n2 += x00;
                float nrm = sqrtf(fmaxf(n2, 0.f));
                nrm = fmaxf(nrm, 1e-12f);
                g_norm[bc * 9 + kh * 3 + kw] = nrm;
            }
    }
}

// ---------------------------------------------------------------------------
// Kernel 2: build split-bf16 normalized unfold, transposed to [b][n][hi|lo].
// ---------------------------------------------------------------------------
__global__ void splitz_kernel(const float* __restrict__ x) {
    __shared__ float tl[32][33];
    const int b = blockIdx.z, d0 = blockIdx.y * 32, n0 = blockIdx.x * 32;
    const int tx = threadIdx.x, ty = threadIdx.y;   // 32x8
    #pragma unroll
    for (int i = 0; i < 4; ++i) {
        const int d = d0 + ty + i * 8, n = n0 + tx;
        const int c = d / 9, jj = d - c * 9;
        const int h = (n >> 6) + jj / 3 - 1, w = (n & 63) + jj % 3 - 1;
        float v = 0.f;
        if ((unsigned)h < 64u && (unsigned)w < 64u)
            v = __fdiv_rn(x[(((size_t)b * NC + c) * 64 + h) * 64 + w],
                          g_norm[(b * NC + c) * 9 + jj]);
        tl[ty + i * 8][tx] = v;
    }
    __syncthreads();
    #pragma unroll
    for (int i = 0; i < 4; ++i) {
        const int n = n0 + ty + i * 8, d = d0 + tx;
        const float z = tl[tx][ty + i * 8];
        const __nv_bfloat16 h = __float2bfloat16(z);
        const __nv_bfloat16 l = __float2bfloat16(z - __bfloat162float(h));
        __nv_bfloat16* row = g_za + ((size_t)b * NHW + n) * KP;
        row[d] = h;
        row[576 + d] = l;
    }
}

// ---------------------------------------------------------------------------
// Kernel 3: persistent HMMA bf16 split GEMM over upper-triangular 128x128
// tiles of the symmetric R, with per-tile row+col top-3 candidate scans.
// 256 threads, 8 warps as 4x2, warp tile 32x64, 3-stage cp.async pipeline.
// ---------------------------------------------------------------------------
__device__ __forceinline__ void issue_chunk(const char* zb, int n0, int m0,
                                            int kc, int stg, uint32_t smb, int tid) {
    const int seg = kc / 9, sub = kc - seg * 9;
    const int aoff2 = (((seg == 1) ? 576 : 0) + sub * 64) * 2;  // bytes
    const int boff2 = (((seg == 2) ? 576 : 0) + sub * 64) * 2;
    const uint32_t sA = smb + stg * STAGE;
    const uint32_t sB = sA + 16384;
    #pragma unroll
    for (int i = 0; i < 4; ++i) {           // A: 128 rows x 128 B
        const int s = tid + i * 256, row = s >> 3, cb = (s & 7) * 16;
        cp16(sA + row * 128 + (cb ^ ((row & 7) << 4)),
             zb + (size_t)(n0 + row) * ROWB + aoff2 + cb);
    }
    #pragma unroll
    for (int i = 0; i < 4; ++i) {           // B: 128 rows x 128 B
        const int s = tid + i * 256, row = s >> 3, cb = (s & 7) * 16;
        cp16(sB + row * 128 + (cb ^ ((row & 7) << 4)),
             zb + (size_t)(m0 + row) * ROWB + boff2 + cb);
    }
}

__global__ __launch_bounds__(256, 2) void gemm_top3_sym() {
    extern __shared__ char sm[];
    const int tid = threadIdx.x, wid = tid >> 5, lane = tid & 31;
    const uint32_t smb = s2u(sm);

    const int wr = wid >> 1, wc = wid & 1;    // warp tile: rows wr*32, cols wc*64
    const int quad = lane >> 3, qr = lane & 7;
    const uint32_t sw = (uint32_t)qr << 4;

    const int arow0 = wr * 32 + (quad & 1) * 8 + qr;     // + a*16
    const int akb   = (quad >> 1) * 16;
    const int brow0 = wc * 64 + (quad >> 1) * 8 + qr;    // + njp*16
    const int bkb   = (quad & 1) * 16;

    for (int t = blockIdx.x; t < NTILE; t += gridDim.x) {
        const int b = t / NPAIR;
        const int p = t - b * NPAIR;
        int I = 0, rem = p;
        while (rem >= NBLK - I) { rem -= NBLK - I; ++I; }
        const int J = I + rem;
        const int n0 = I * 128, m0 = J * 128;
        const char* zb = (const char*)g_za + (size_t)b * NHW * ROWB;

        float acc[2][8][4];
        #pragma unroll
        for (int a = 0; a < 2; ++a)
            #pragma unroll
            for (int nj = 0; nj < 8; ++nj)
                #pragma unroll
                for (int q = 0; q < 4; ++q) acc[a][nj][q] = 0.f;

        // Prologue: stages 0,1
        issue_chunk(zb, n0, m0, 0, 0, smb, tid); CP_COMMIT();
        issue_chunk(zb, n0, m0, 1, 1, smb, tid); CP_COMMIT();

        for (int kc = 0; kc < NCHUNK; ++kc) {
            CP_WAIT1();             // chunk kc resident
            __syncthreads();        // all warps done reading stage (kc+2)%3
            if (kc + 2 < NCHUNK)
                issue_chunk(zb, n0, m0, kc + 2, (kc + 2) % 3, smb, tid);
            CP_COMMIT();            // unconditional: uniform group counting

            const uint32_t sA = smb + (kc % 3) * STAGE;
            const uint32_t sB = sA + 16384;
            #pragma unroll
            for (int ks = 0; ks < 4; ++ks) {
                uint32_t aF[2][4];
                #pragma unroll
                for (int a = 0; a < 2; ++a) {
                    const uint32_t kb = (uint32_t)(ks * 32 + akb) ^ sw;
                    LDSM4(aF[a][0], aF[a][1], aF[a][2], aF[a][3],
                          sA + (uint32_t)(arow0 + a * 16) * 128 + kb);
                }
                #pragma unroll
                for (int njp = 0; njp < 4; ++njp) {
                    uint32_t b0, b1, b2, b3;
                    const uint32_t kb = (uint32_t)(ks * 32 + bkb) ^ sw;
                    LDSM4(b0, b1, b2, b3,
                          sB + (uint32_t)(brow0 + njp * 16) * 128 + kb);
                    mma16816(acc[0][njp * 2],     aF[0][0], aF[0][1], aF[0][2], aF[0][3], b0, b1);
                    mma16816(acc[0][njp * 2 + 1], aF[0][0], aF[0][1], aF[0][2], aF[0][3], b2, b3);
                    mma16816(acc[1][njp * 2],     aF[1][0], aF[1][1], aF[1][2], aF[1][3], b0, b1);
                    mma16816(acc[1][njp * 2 + 1], aF[1][0], aF[1][1], aF[1][2], aF[1][3], b2, b3);
                }
            }
        }

        // Epilogue: dump tile to smem [128][ESTRIDE], then row & col scans.
        __syncthreads();
        float* tt = (float*)sm;
        {
            const int r1 = wr * 32 + (lane >> 2);
            const int cp = wc * 64 + (lane & 3) * 2;
            #pragma unroll
            for (int a = 0; a < 2; ++a)
                #pragma unroll
                for (int nj = 0; nj < 8; ++nj) {
                    const int rr = r1 + a * 16;
                    const int cc = cp + nj * 8;
                    *(float2*)&tt[rr * ESTRIDE + cc]       = *(float2*)&acc[a][nj][0];
                    *(float2*)&tt[(rr + 8) * ESTRIDE + cc] = *(float2*)&acc[a][nj][2];
                }
        }
        __syncthreads();

        // threads 0..127: row scan (row tid), slot J; threads 128..255: col
        // scan (col tid-128), slot I (skip on diagonal).
        {
            const bool isrow = tid < 128;
            if (isrow || I != J) {
                const int e = isrow ? tid : tid - 128;
                float b0v = -1e30f, b1v = -1e30f, b2v = -1e30f;
                int   j0 = 0, j1 = 0, j2 = 0;
                #pragma unroll 4
                for (int u = 0; u < 128; ++u) {
                    const float v = isrow ? tt[e * ESTRIDE + u] : tt[u * ESTRIDE + e];
                    if (v > b2v) {
                        if (v > b1v) {
                            if (v > b0v) {
                                b2v = b1v; j2 = j1;
                                b1v = b0v; j1 = j0;
                                b0v = v;   j0 = u;
                            } else {
                                b2v = b1v; j2 = j1;
                                b1v = v;   j1 = u;
                            }
                        } else {
                            b2v = v; j2 = u;
                        }
                    }
                }
                const int row  = isrow ? (n0 + e) : (m0 + e);
                const int moff = isrow ? m0 : n0;
                const int slot = isrow ? J : I;
                const size_t o = (((size_t)b * NHW + row) * NBLK + slot) * 3;
                g_cv[o] = b0v;       g_cv[o + 1] = b1v;       g_cv[o + 2] = b2v;
                g_ci[o] = moff + j0; g_ci[o + 1] = moff + j1; g_ci[o + 2] = moff + j2;
            }
        }
        __syncthreads();   // epilogue reads done before next tile's cp.async
    }
}

// ---------------------------------------------------------------------------
// Kernel 4: attention epilogue with in-warp candidate merge.
// One warp per (b,n); lane l merges candidate slot l via butterfly shuffles
// (value desc, tie -> lower index). Channels paired per lane (2l, 2l+1):
// bf16x2 loads from g_za, float2 output stores. Q staged per-block in smem.
// ---------------------------------------------------------------------------
__device__ __forceinline__ void ins3(float& v0, float& v1, float& v2,
                                     int& i0, int& i1, int& i2,
                                     float w, int y) {
    if (w > v2 || (w == v2 && y < i2)) {
        if (w > v1 || (w == v1 && y < i1)) {
            if (w > v0 || (w == v0 && y < i0)) {
                v2 = v1; i2 = i1;
                v1 = v0; i1 = i0;
                v0 = w;  i0 = y;
            } else {
                v2 = v1; i2 = i1;
                v1 = w;  i1 = y;
            }
        } else {
            v2 = w; i2 = y;
        }
    }
}

__global__ void attn_kernel(const float* __restrict__ x, float* __restrict__ out) {
    __shared__ float qs[8][66];
    const int tid = threadIdx.x, wid = tid >> 5, lane = tid & 31;
    const int idx0 = blockIdx.x * 8;             // first (b,n) of this block
    const int b = idx0 >> 12;
    const int n0 = idx0 & (NHW - 1);

    // Stage Q: [8 n][64 c], coalesced-ish reads from x[b][c][n]
    {
        const int c = tid >> 3, j = tid & 7;
        qs[j][c]      = x[((size_t)b * NC + c) * NHW + n0 + j];
        qs[j][c + 32] = x[((size_t)b * NC + c + 32) * NHW + n0 + j];
    }
    __syncthreads();

    const int n = n0 + wid;
    const int gw = idx0 + wid;
    const int c0 = lane * 2;

    const float2 q = *(const float2*)&qs[wid][c0];

    // In-warp merge of 32 candidate slots (lane l -> slot l)
    float v0, v1, v2;
    int   i0, i1, i2;
    {
        const size_t o = (((size_t)b * NHW + n) * NBLK + lane) * 3;
        v0 = g_cv[o]; v1 = g_cv[o + 1]; v2 = g_cv[o + 2];
        i0 = g_ci[o]; i1 = g_ci[o + 1]; i2 = g_ci[o + 2];
        #pragma unroll
        for (int o2 = 16; o2 > 0; o2 >>= 1) {
            const float w0 = __shfl_xor_sync(0xffffffffu, v0, o2);
            const float w1 = __shfl_xor_sync(0xffffffffu, v1, o2);
            const float w2 = __shfl_xor_sync(0xffffffffu, v2, o2);
            const int   y0 = __shfl_xor_sync(0xffffffffu, i0, o2);
            const int   y1 = __shfl_xor_sync(0xffffffffu, i1, o2);
            const int   y2 = __shfl_xor_sync(0xffffffffu, i2, o2);
            ins3(v0, v1, v2, i0, i1, i2, w0, y0);
            ins3(v0, v1, v2, i0, i1, i2, w1, y1);
            ins3(v0, v1, v2, i0, i1, i2, w2, y2);
        }
    }
    const int mi[3] = {i0, i1, i2};

    // Gather K (hi+lo reconstruct), channels (c0, c0+1) per lane
    float kv0[27], kv1[27];
    #pragma unroll
    for (int k = 0; k < 3; ++k) {
        const __nv_bfloat16* __restrict__ row =
            g_za + ((size_t)b * NHW + mi[k]) * KP;
        #pragma unroll
        for (int r = 0; r < 9; ++r) {
            const int d = r * 64 + c0;
            const __nv_bfloat162 hi = *(const __nv_bfloat162*)(row + d);
            const __nv_bfloat162 lo = *(const __nv_bfloat162*)(row + 576 + d);
            kv0[k * 9 + r] = __bfloat162float(hi.x) + __bfloat162float(lo.x);
            kv1[k * 9 + r] = __bfloat162float(hi.y) + __bfloat162float(lo.y);
        }
    }

    float s[27];
    #pragma unroll
    for (int e = 0; e < 27; ++e) {
        float t = q.x * kv0[e] + q.y * kv1[e];
        #pragma unroll
        for (int o = 16; o > 0; o >>= 1) t += __shfl_xor_sync(0xffffffffu, t, o);
        s[e] = t * 0.125f;   // / sqrt(64)
    }

    float mx = s[0];
    #pragma unroll
    for (int e = 1; e < 27; ++e) mx = fmaxf(mx, s[e]);
    float sum = 0.f;
    #pragma unroll
    for (int e = 0; e < 27; ++e) { s[e] = expf(s[e] - mx); sum += s[e]; }

    float o0 = 0.f, o1 = 0.f;
    #pragma unroll
    for (int e = 0; e < 27; ++e) {
        const float we = __fdiv_rn(s[e], sum);
        o0 += we * kv0[e];
        o1 += we * kv1[e];
    }
    *(float2*)&out[(size_t)gw * 64 + c0] = make_float2(o0, o1);
}

// ---------------------------------------------------------------------------
extern "C" void kernel_launch(void* const* d_in, const int* in_sizes, int n_in,
                              void* d_out, int out_size) {
    const float* x = (const float*)d_in[0];
    float* out = (float*)d_out;

    int dev = 0, sms = 148;
    cudaGetDevice(&dev);
    cudaDeviceGetAttribute(&sms, cudaDevAttrMultiProcessorCount, dev);

    norms_kernel<<<NB * NC, 256>>>(x);
    splitz_kernel<<<dim3(NHW / 32, NKD / 32, NB), dim3(32, 8)>>>(x);

    cudaFuncSetAttribute(gemm_top3_sym,
                         cudaFuncAttributeMaxDynamicSharedMemorySize, SMEMB);
    gemm_top3_sym<<<2 * sms, 256, SMEMB>>>();

    attn_kernel<<<NB * NHW / 8, 256>>>(x, out);
}

// round 15
// speedup vs baseline: 1.2585x; 1.2585x over previous
#include <cuda_runtime.h>
#include <cuda_bf16.h>
#include <math.h>
#include <stdint.h>

// Problem constants
constexpr int NB  = 4;
constexpr int NC  = 64;
constexpr int NHW = 4096;     // 64*64
constexpr int NKD = 576;      // C*9
constexpr int NBLK = 32;      // 4096 / 128 row-blocks
constexpr int NPAIR = NBLK * (NBLK + 1) / 2;   // 528 upper-tri tiles

// Phase-A GEMM config: hi-only bf16 (screening pass)
constexpr int KP     = 1152;          // stored K' = [hi(576) | lo(576)]
constexpr int ROWB   = KP * 2;        // 2304 bytes per n-row
constexpr int NCHUNK = 9;             // 9 x 64 = K 576 (hi segment only)
constexpr int NCAND  = 6;             // per-tile top-6 candidates per row/col
constexpr int NREF   = 10;            // refine top-10 exactly

constexpr int STAGE  = 32768;         // A 16KB + B 16KB per stage
constexpr int SMEMB  = 3 * STAGE;     // 96 KB, 3-stage pipeline
constexpr int ESTRIDE = 130;          // epilogue smem row stride (floats)

// Scratch (static __device__: no allocations allowed)
__device__ __nv_bfloat16 g_za[(size_t)NB * NHW * KP];      // [b][n][hi|lo] ~37.7MB
__device__ float g_norm[NB * NC * 9];                      // per-(b,c,j) L2 norms
__device__ float g_cv[(size_t)NB * NHW * NBLK * NCAND];    // cand values  12.6MB
__device__ int   g_ci[(size_t)NB * NHW * NBLK * NCAND];    // cand indices 12.6MB
__device__ int   g_top[NB * NHW * 3];                      // exact top-3 per (b,n)

// ---------------------------------------------------------------------------
// PTX helpers (sm_80-era: safe for plain sm_103 ptxas target)
// ---------------------------------------------------------------------------
__device__ __forceinline__ uint32_t s2u(const void* p) {
    uint32_t a;
    asm("{ .reg .u64 t; cvta.to.shared.u64 t, %1; cvt.u32.u64 %0, t; }"
        : "=r"(a) : "l"(p));
    return a;
}
__device__ __forceinline__ void cp16(uint32_t s, const void* g) {
    asm volatile("cp.async.cg.shared.global [%0], [%1], 16;"
                 :: "r"(s), "l"(g) : "memory");
}
#define CP_COMMIT()  asm volatile("cp.async.commit_group;" ::: "memory")
#define CP_WAIT1()   asm volatile("cp.async.wait_group 1;" ::: "memory")

#define LDSM4(r0, r1, r2, r3, a) \
    asm volatile("ldmatrix.sync.aligned.m8n8.x4.shared.b16 {%0,%1,%2,%3}, [%4];" \
                 : "=r"(r0), "=r"(r1), "=r"(r2), "=r"(r3) : "r"(a))

__device__ __forceinline__ void mma16816(float* c, uint32_t a0, uint32_t a1,
                                         uint32_t a2, uint32_t a3,
                                         uint32_t b0, uint32_t b1) {
    asm volatile(
        "mma.sync.aligned.m16n8k16.row.col.f32.bf16.bf16.f32 "
        "{%0,%1,%2,%3}, {%4,%5,%6,%7}, {%8,%9}, {%0,%1,%2,%3};"
        : "+f"(c[0]), "+f"(c[1]), "+f"(c[2]), "+f"(c[3])
        : "r"(a0), "r"(a1), "r"(a2), "r"(a3), "r"(b0), "r"(b1));
}

// ---------------------------------------------------------------------------
// Kernel 1: shifted norms via border decomposition.
// ---------------------------------------------------------------------------
__global__ void norms_kernel(const float* __restrict__ x) {
    const int bc = blockIdx.x;
    const float* xp = x + (size_t)bc * NHW;

    float s = 0.f, r0 = 0.f, r63 = 0.f, cl = 0.f, cr = 0.f;
    for (int idx = threadIdx.x; idx < NHW; idx += blockDim.x) {
        float v = xp[idx]; v *= v;
        const int h = idx >> 6, w = idx & 63;
        s += v;
        if (h == 0)  r0  += v;
        if (h == 63) r63 += v;
        if (w == 0)  cl  += v;
        if (w == 63) cr  += v;
    }
    __shared__ float red[5][256];
    red[0][threadIdx.x] = s;  red[1][threadIdx.x] = r0; red[2][threadIdx.x] = r63;
    red[3][threadIdx.x] = cl; red[4][threadIdx.x] = cr;
    __syncthreads();
    for (int o = 128; o > 0; o >>= 1) {
        if (threadIdx.x < o)
            for (int q = 0; q < 5; ++q) red[q][threadIdx.x] += red[q][threadIdx.x + o];
        __syncthreads();
    }
    if (threadIdx.x == 0) {
        const float S = red[0][0], R0 = red[1][0], R63 = red[2][0];
        const float CL = red[3][0], CR = red[4][0];
        float x00 = xp[0],        x0e = xp[63];
        float xe0 = xp[63 * 64],  xee = xp[63 * 64 + 63];
        x00 *= x00; x0e *= x0e; xe0 *= xe0; xee *= xee;
        #pragma unroll
        for (int kh = 0; kh < 3; ++kh)
            #pragma unroll
            for (int kw = 0; kw < 3; ++kw) {
                float n2 = S;
                if (kh == 0) n2 -= R63;
                if (kh == 2) n2 -= R0;
                if (kw == 0) n2 -= CR;
                if (kw == 2) n2 -= CL;
                if (kh == 0 && kw == 0) n2 += xee;
                if (kh == 0 && kw == 2) n2 += xe0;
                if (kh == 2 && kw == 0) n2 += x0e;
                if (kh == 2 && kw == 2) n2 += x00;
                float nrm = sqrtf(fmaxf(n2, 0.f));
                nrm = fmaxf(nrm, 1e-12f);
                g_norm[bc * 9 + kh * 3 + kw] = nrm;
            }
    }
}

// ---------------------------------------------------------------------------
// Kernel 2: build split-bf16 normalized unfold, transposed to [b][n][hi|lo].
// ---------------------------------------------------------------------------
__global__ void splitz_kernel(const float* __restrict__ x) {
    __shared__ float tl[32][33];
    const int b = blockIdx.z, d0 = blockIdx.y * 32, n0 = blockIdx.x * 32;
    const int tx = threadIdx.x, ty = threadIdx.y;   // 32x8
    #pragma unroll
    for (int i = 0; i < 4; ++i) {
        const int d = d0 + ty + i * 8, n = n0 + tx;
        const int c = d / 9, jj = d - c * 9;
        const int h = (n >> 6) + jj / 3 - 1, w = (n & 63) + jj % 3 - 1;
        float v = 0.f;
        if ((unsigned)h < 64u && (unsigned)w < 64u)
            v = __fdiv_rn(x[(((size_t)b * NC + c) * 64 + h) * 64 + w],
                          g_norm[(b * NC + c) * 9 + jj]);
        tl[ty + i * 8][tx] = v;
    }
    __syncthreads();
    #pragma unroll
    for (int i = 0; i < 4; ++i) {
        const int n = n0 + ty + i * 8, d = d0 + tx;
        const float z = tl[tx][ty + i * 8];
        const __nv_bfloat16 h = __float2bfloat16(z);
        const __nv_bfloat16 l = __float2bfloat16(z - __bfloat162float(h));
        __nv_bfloat16* row = g_za + ((size_t)b * NHW + n) * KP;
        row[d] = h;
        row[576 + d] = l;
    }
}

// ---------------------------------------------------------------------------
// Kernel 3 (Phase A): hi-only bf16 screening GEMM on upper-triangular
// 128x128 tiles of symmetric R; per-tile row+col top-6 candidate scans.
// 256 threads, 8 warps 4x2, warp tile 32x64, 3-stage cp.async pipeline.
// ---------------------------------------------------------------------------
__device__ __forceinline__ void issue_chunk(const char* zb, int n0, int m0,
                                            int kc, int stg, uint32_t smb, int tid) {
    const int off2 = kc * 128;   // hi segment, 64 elems * 2B per chunk
    const uint32_t sA = smb + stg * STAGE;
    const uint32_t sB = sA + 16384;
    #pragma unroll
    for (int i = 0; i < 4; ++i) {           // A: 128 rows x 128 B
        const int s = tid + i * 256, row = s >> 3, cb = (s & 7) * 16;
        cp16(sA + row * 128 + (cb ^ ((row & 7) << 4)),
             zb + (size_t)(n0 + row) * ROWB + off2 + cb);
    }
    #pragma unroll
    for (int i = 0; i < 4; ++i) {           // B: 128 rows x 128 B
        const int s = tid + i * 256, row = s >> 3, cb = (s & 7) * 16;
        cp16(sB + row * 128 + (cb ^ ((row & 7) << 4)),
             zb + (size_t)(m0 + row) * ROWB + off2 + cb);
    }
}

__global__ __launch_bounds__(256, 2) void gemm_screen() {
    extern __shared__ char sm[];
    const int tid = threadIdx.x, wid = tid >> 5, lane = tid & 31;
    const int b = blockIdx.y;
    int I = 0, rem = blockIdx.x;
    while (rem >= NBLK - I) { rem -= NBLK - I; ++I; }
    const int J = I + rem;
    const int n0 = I * 128, m0 = J * 128;
    const char* zb = (const char*)g_za + (size_t)b * NHW * ROWB;
    const uint32_t smb = s2u(sm);

    const int wr = wid >> 1, wc = wid & 1;    // warp tile: rows wr*32, cols wc*64
    const int quad = lane >> 3, qr = lane & 7;
    const uint32_t sw = (uint32_t)qr << 4;

    const int arow0 = wr * 32 + (quad & 1) * 8 + qr;
    const int akb   = (quad >> 1) * 16;
    const int brow0 = wc * 64 + (quad >> 1) * 8 + qr;
    const int bkb   = (quad & 1) * 16;

    float acc[2][8][4];
    #pragma unroll
    for (int a = 0; a < 2; ++a)
        #pragma unroll
        for (int nj = 0; nj < 8; ++nj)
            #pragma unroll
            for (int q = 0; q < 4; ++q) acc[a][nj][q] = 0.f;

    issue_chunk(zb, n0, m0, 0, 0, smb, tid); CP_COMMIT();
    issue_chunk(zb, n0, m0, 1, 1, smb, tid); CP_COMMIT();

    for (int kc = 0; kc < NCHUNK; ++kc) {
        CP_WAIT1();
        __syncthreads();
        if (kc + 2 < NCHUNK)
            issue_chunk(zb, n0, m0, kc + 2, (kc + 2) % 3, smb, tid);
        CP_COMMIT();

        const uint32_t sA = smb + (kc % 3) * STAGE;
        const uint32_t sB = sA + 16384;
        #pragma unroll
        for (int ks = 0; ks < 4; ++ks) {
            uint32_t aF[2][4];
            #pragma unroll
            for (int a = 0; a < 2; ++a) {
                const uint32_t kb = (uint32_t)(ks * 32 + akb) ^ sw;
                LDSM4(aF[a][0], aF[a][1], aF[a][2], aF[a][3],
                      sA + (uint32_t)(arow0 + a * 16) * 128 + kb);
            }
            #pragma unroll
            for (int njp = 0; njp < 4; ++njp) {
                uint32_t b0, b1, b2, b3;
                const uint32_t kb = (uint32_t)(ks * 32 + bkb) ^ sw;
                LDSM4(b0, b1, b2, b3,
                      sB + (uint32_t)(brow0 + njp * 16) * 128 + kb);
                mma16816(acc[0][njp * 2],     aF[0][0], aF[0][1], aF[0][2], aF[0][3], b0, b1);
                mma16816(acc[0][njp * 2 + 1], aF[0][0], aF[0][1], aF[0][2], aF[0][3], b2, b3);
                mma16816(acc[1][njp * 2],     aF[1][0], aF[1][1], aF[1][2], aF[1][3], b0, b1);
                mma16816(acc[1][njp * 2 + 1], aF[1][0], aF[1][1], aF[1][2], aF[1][3], b2, b3);
            }
        }
    }

    // Epilogue: dump tile to smem [128][ESTRIDE], then row & col top-6 scans.
    __syncthreads();
    float* tt = (float*)sm;
    {
        const int r1 = wr * 32 + (lane >> 2);
        const int cp = wc * 64 + (lane & 3) * 2;
        #pragma unroll
        for (int a = 0; a < 2; ++a)
            #pragma unroll
            for (int nj = 0; nj < 8; ++nj) {
                const int rr = r1 + a * 16;
                const int cc = cp + nj * 8;
                *(float2*)&tt[rr * ESTRIDE + cc]       = *(float2*)&acc[a][nj][0];
                *(float2*)&tt[(rr + 8) * ESTRIDE + cc] = *(float2*)&acc[a][nj][2];
            }
    }
    __syncthreads();

    // threads 0..127: row scan (row tid) -> slot J; threads 128..255: col scan
    // (col tid-128) -> slot I (skip on diagonal). Top-6, sorted desc, stable.
    {
        const bool isrow = tid < 128;
        if (isrow || I != J) {
            const int e = isrow ? tid : tid - 128;
            float bv[NCAND];
            int   bi[NCAND];
            #pragma unroll
            for (int s = 0; s < NCAND; ++s) { bv[s] = -1e30f; bi[s] = 0; }
            for (int u = 0; u < 128; ++u) {
                const float v = isrow ? tt[e * ESTRIDE + u] : tt[u * ESTRIDE + e];
                if (v > bv[NCAND - 1]) {
                    bv[NCAND - 1] = v; bi[NCAND - 1] = u;
                    #pragma unroll
                    for (int s = NCAND - 1; s > 0; --s)
                        if (bv[s] > bv[s - 1]) {
                            const float tv = bv[s]; bv[s] = bv[s - 1]; bv[s - 1] = tv;
                            const int   ty = bi[s]; bi[s] = bi[s - 1]; bi[s - 1] = ty;
                        }
                }
            }
            const int row  = isrow ? (n0 + e) : (m0 + e);
            const int moff = isrow ? m0 : n0;
            const int slot = isrow ? J : I;
            const size_t o = (((size_t)b * NHW + row) * NBLK + slot) * NCAND;
            #pragma unroll
            for (int s = 0; s < NCAND; ++s) {
                g_cv[o + s] = bv[s];
                g_ci[o + s] = moff + bi[s];
            }
        }
    }
}

// ---------------------------------------------------------------------------
// Kernel 3b (Phase B): per-row k-way merge of 32 sorted top-6 lists ->
// approx top-10 -> exact fp32 recompute (hi+lo) -> exact top-3.
// One warp per (b,n).
// ---------------------------------------------------------------------------
__global__ void refine_kernel() {
    const int gw = (blockIdx.x * blockDim.x + threadIdx.x) >> 5;
    const int lane = threadIdx.x & 31;
    if (gw >= NB * NHW) return;
    const int b = gw >> 12;
    const int n = gw & (NHW - 1);

    // Load my slot's sorted candidate list
    float cv[NCAND]; int ci[NCAND];
    {
        const size_t o = (((size_t)b * NHW + n) * NBLK + lane) * NCAND;
        #pragma unroll
        for (int s = 0; s < NCAND; ++s) { cv[s] = g_cv[o + s]; ci[s] = g_ci[o + s]; }
    }

    // 32-way merge by warp-argmax (value desc, tie -> lower m)
    int ptr = 0;
    float curv = cv[0];
    int   curi = ci[0];
    int top_m[NREF];
    #pragma unroll
    for (int t = 0; t < NREF; ++t) {
        float v = curv; int m = curi;
        #pragma unroll
        for (int o2 = 16; o2 > 0; o2 >>= 1) {
            const float vv = __shfl_xor_sync(0xffffffffu, v, o2);
            const int   mm = __shfl_xor_sync(0xffffffffu, m, o2);
            if (vv > v || (vv == v && mm < m)) { v = vv; m = mm; }
        }
        top_m[t] = m;                      // identical on all lanes
        if (curi == m) {                   // m unique across lanes
            ++ptr;
            if (ptr < NCAND) { curv = cv[ptr]; curi = ci[ptr]; }
            else             { curv = -1e38f; curi = 0x7fffffff; }
        }
    }

    // Reconstruct my 18-element slice of z(n)
    const __nv_bfloat16* rn = g_za + ((size_t)b * NHW + n) * KP;
    float zn[18];
    {
        const __nv_bfloat162* rh = (const __nv_bfloat162*)(rn + lane * 18);
        const __nv_bfloat162* rl = (const __nv_bfloat162*)(rn + 576 + lane * 18);
        #pragma unroll
        for (int i = 0; i < 9; ++i) {
            const __nv_bfloat162 h = rh[i], l = rl[i];
            zn[2 * i]     = __bfloat162float(h.x) + __bfloat162float(l.x);
            zn[2 * i + 1] = __bfloat162float(h.y) + __bfloat162float(l.y);
        }
    }

    // Exact dots for the NREF candidates (butterfly sum -> identical all lanes)
    float sv[NREF];
    #pragma unroll
    for (int t = 0; t < NREF; ++t) {
        const __nv_bfloat16* rm = g_za + ((size_t)b * NHW + top_m[t]) * KP;
        const __nv_bfloat162* ch = (const __nv_bfloat162*)(rm + lane * 18);
        const __nv_bfloat162* cl = (const __nv_bfloat162*)(rm + 576 + lane * 18);
        float s = 0.f;
        #pragma unroll
        for (int i = 0; i < 9; ++i) {
            const __nv_bfloat162 h = ch[i], l = cl[i];
            const float a0 = __bfloat162float(h.x) + __bfloat162float(l.x);
            const float a1 = __bfloat162float(h.y) + __bfloat162float(l.y);
            s += zn[2 * i] * a0 + zn[2 * i + 1] * a1;
        }
        #pragma unroll
        for (int o2 = 16; o2 > 0; o2 >>= 1)
            s += __shfl_xor_sync(0xffffffffu, s, o2);
        sv[t] = s;
    }

    // Exact top-3 of NREF (value desc, tie -> lower m); identical on all lanes
    float b0v = -1e30f, b1v = -1e30f, b2v = -1e30f;
    int   j0 = 0x7fffffff, j1 = 0x7fffffff, j2 = 0x7fffffff;
    #pragma unroll
    for (int t = 0; t < NREF; ++t) {
        const float v = sv[t];
        const int   m = top_m[t];
        if (v > b2v || (v == b2v && m < j2)) {
            if (v > b1v || (v == b1v && m < j1)) {
                if (v > b0v || (v == b0v && m < j0)) {
                    b2v = b1v; j2 = j1;
                    b1v = b0v; j1 = j0;
                    b0v = v;   j0 = m;
                } else {
                    b2v = b1v; j2 = j1;
                    b1v = v;   j1 = m;
                }
            } else {
                b2v = v; j2 = m;
            }
        }
    }
    if (lane == 0) {
        g_top[gw * 3] = j0; g_top[gw * 3 + 1] = j1; g_top[gw * 3 + 2] = j2;
    }
}

// ---------------------------------------------------------------------------
// Kernel 4: attention epilogue. K from g_za (hi+lo), bf16x2 loads; Q staged
// per-block in smem; float2 output stores. One warp per (b,n).
// ---------------------------------------------------------------------------
__global__ void attn_kernel(const float* __restrict__ x, float* __restrict__ out) {
    __shared__ float qs[8][66];
    const int tid = threadIdx.x, wid = tid >> 5, lane = tid & 31;
    const int idx0 = blockIdx.x * 8;             // first (b,n) of this block
    const int b = idx0 >> 12;
    const int n0 = idx0 & (NHW - 1);

    {
        const int c = tid >> 3, j = tid & 7;
        qs[j][c]      = x[((size_t)b * NC + c) * NHW + n0 + j];
        qs[j][c + 32] = x[((size_t)b * NC + c + 32) * NHW + n0 + j];
    }
    __syncthreads();

    const int gw = idx0 + wid;
    const int c0 = lane * 2;
    const float2 q = *(const float2*)&qs[wid][c0];

    int mi[3];
    mi[0] = g_top[gw * 3];
    mi[1] = g_top[gw * 3 + 1];
    mi[2] = g_top[gw * 3 + 2];

    float kv0[27], kv1[27];
    #pragma unroll
    for (int k = 0; k < 3; ++k) {
        const __nv_bfloat16* __restrict__ row =
            g_za + ((size_t)b * NHW + mi[k]) * KP;
        #pragma unroll
        for (int r = 0; r < 9; ++r) {
            const int d = r * 64 + c0;
            const __nv_bfloat162 hi = *(const __nv_bfloat162*)(row + d);
            const __nv_bfloat162 lo = *(const __nv_bfloat162*)(row + 576 + d);
            kv0[k * 9 + r] = __bfloat162float(hi.x) + __bfloat162float(lo.x);
            kv1[k * 9 + r] = __bfloat162float(hi.y) + __bfloat162float(lo.y);
        }
    }

    float s[27];
    #pragma unroll
    for (int e = 0; e < 27; ++e) {
        float t = q.x * kv0[e] + q.y * kv1[e];
        #pragma unroll
        for (int o = 16; o > 0; o >>= 1) t += __shfl_xor_sync(0xffffffffu, t, o);
        s[e] = t * 0.125f;   // / sqrt(64)
    }

    float mx = s[0];
    #pragma unroll
    for (int e = 1; e < 27; ++e) mx = fmaxf(mx, s[e]);
    float sum = 0.f;
    #pragma unroll
    for (int e = 0; e < 27; ++e) { s[e] = expf(s[e] - mx); sum += s[e]; }

    float o0 = 0.f, o1 = 0.f;
    #pragma unroll
    for (int e = 0; e < 27; ++e) {
        const float we = __fdiv_rn(s[e], sum);
        o0 += we * kv0[e];
        o1 += we * kv1[e];
    }
    *(float2*)&out[(size_t)gw * 64 + c0] = make_float2(o0, o1);
}

// ---------------------------------------------------------------------------
extern "C" void kernel_launch(void* const* d_in, const int* in_sizes, int n_in,
                              void* d_out, int out_size) {
    const float* x = (const float*)d_in[0];
    float* out = (float*)d_out;

    norms_kernel<<<NB * NC, 256>>>(x);
    splitz_kernel<<<dim3(NHW / 32, NKD / 32, NB), dim3(32, 8)>>>(x);

    cudaFuncSetAttribute(gemm_screen,
                         cudaFuncAttributeMaxDynamicSharedMemorySize, SMEMB);
    gemm_screen<<<dim3(NPAIR, NB), 256, SMEMB>>>();

    refine_kernel<<<(NB * NHW * 32 + 255) / 256, 256>>>();
    attn_kernel<<<NB * NHW / 8, 256>>>(x, out);
}